// round 7
// baseline (speedup 1.0000x reference)
#include <cuda_runtime.h>
#include <cuda_bf16.h>

#define Bn 4
#define Cc 256
#define Pp 64
#define Hh 4
#define Dd 16
#define Nn 4096

typedef unsigned long long ull;
typedef unsigned int uint;

// Scratch (device globals; no allocation allowed)
__device__ float g_proj[6 * Bn * Pp * Nn];   // [proj_id][b][p][n]
__device__ float g_attn[2 * Bn * Pp * Nn];   // [branch][b][p][n]
__device__ float g_part[8 * 16 * 64 * 2];    // per (z,group,ntile): s, s2
__device__ float g_stats[2 * Bn * 16 * 2];   // mean, rstd per (branch,b,group)

struct ProjArgs {
    const float* x[2];
    const float* w[6];
    const float* b[6];
};

// ---- packed f32x2 ops (FMA pipe) ----
#define PFMA(d, a, b, c) asm("fma.rn.f32x2 %0,%1,%2,%3;" : "=l"(d) : "l"(a), "l"(b), "l"(c))
#define PADD(d, a, b)    asm("add.rn.f32x2 %0,%1,%2;"    : "=l"(d) : "l"(a), "l"(b))

__device__ __forceinline__ ull fdup(float x) {
    uint u = __float_as_uint(x);
    return ((ull)u << 32) | u;
}
__device__ __forceinline__ ull fpack(float lo, float hi) {
    return ((ull)__float_as_uint(hi) << 32) | __float_as_uint(lo);
}

// packed 2^t (round trick + deg-5 poly + exponent splice); |rel err| < 4e-6
__device__ __forceinline__ ull pexp2(ull t) {
    ull r, fi, f, p;
    PADD(r, t, fdup(12582912.f));
    PADD(fi, r, fdup(-12582912.f));
    PFMA(f, fi, fdup(-1.f), t);
    p = fdup(1.33335581e-3f);
    PFMA(p, p, f, fdup(9.61812911e-3f));
    PFMA(p, p, f, fdup(5.55041087e-2f));
    PFMA(p, p, f, fdup(2.40226507e-1f));
    PFMA(p, p, f, fdup(6.93147181e-1f));
    PFMA(p, p, f, fdup(1.0f));
    uint lo = (uint)p + ((uint)r << 23);
    uint hi = (uint)(p >> 32) + ((uint)(r >> 32) << 23);
    return ((ull)hi << 32) | lo;
}

__device__ __forceinline__ uint smem_u32(const void* p) {
    uint a;
    asm("{ .reg .u64 t; cvta.to.shared.u64 t, %1; cvt.u32.u64 %0, t; }" : "=r"(a) : "l"(p));
    return a;
}

__device__ __forceinline__ uint bfx2(ull p) {
    float lo = __uint_as_float((uint)p);
    float hi = __uint_as_float((uint)(p >> 32));
    uint r;
    asm("cvt.rn.bf16x2.f32 %0, %1, %2;" : "=r"(r) : "f"(hi), "f"(lo));
    return r;
}

#define LDSM_X4(r0, r1, r2, r3, a) \
    asm volatile("ldmatrix.sync.aligned.m8n8.x4.shared.b16 {%0,%1,%2,%3}, [%4];" \
        : "=r"(r0), "=r"(r1), "=r"(r2), "=r"(r3) : "r"(a))
#define LDSM_X2(r0, r1, a) \
    asm volatile("ldmatrix.sync.aligned.m8n8.x2.shared.b16 {%0,%1}, [%2];" \
        : "=r"(r0), "=r"(r1) : "r"(a))
#define LDSM_X2_T(r0, r1, a) \
    asm volatile("ldmatrix.sync.aligned.m8n8.x2.trans.shared.b16 {%0,%1}, [%2];" \
        : "=r"(r0), "=r"(r1) : "r"(a))

__device__ __forceinline__ void mma16816(float* c, const uint* a, const uint* b) {
    asm volatile(
        "mma.sync.aligned.m16n8k16.row.col.f32.bf16.bf16.f32 "
        "{%0,%1,%2,%3}, {%4,%5,%6,%7}, {%8,%9}, {%0,%1,%2,%3};"
        : "+f"(c[0]), "+f"(c[1]), "+f"(c[2]), "+f"(c[3])
        : "r"(a[0]), "r"(a[1]), "r"(a[2]), "r"(a[3]), "r"(b[0]), "r"(b[1]));
}

// ---------------- QKV projection (packed f32x2 inner loop) ----------------
__global__ __launch_bounds__(256) void proj_kernel(ProjArgs a) {
    int pid = blockIdx.z;
    int bb  = blockIdx.y;
    int n0  = blockIdx.x * 64;
    const float* X  = a.x[pid >= 3 ? 1 : 0] + (size_t)bb * Cc * Nn;
    const float* W  = a.w[pid];
    const float* Bi = a.b[pid];

    __shared__ __align__(16) ull  Wd[16][66];
    __shared__ __align__(16) float Xs[16][68];

    int tid = threadIdx.x;
    int tx = tid & 15, ty = tid >> 4;
    ull acc[4][2] = {};

    for (int k0 = 0; k0 < Cc; k0 += 16) {
        {
            int p  = tid >> 2;
            int cc = (tid & 3) << 2;
            float4 wv = *(const float4*)(W + (size_t)p * Cc + k0 + cc);
            Wd[cc + 0][p] = fdup(wv.x); Wd[cc + 1][p] = fdup(wv.y);
            Wd[cc + 2][p] = fdup(wv.z); Wd[cc + 3][p] = fdup(wv.w);
        }
        {
            int kk = ty;
            int nn = tx << 2;
            *(float4*)&Xs[kk][nn] = *(const float4*)(X + (size_t)(k0 + kk) * Nn + n0 + nn);
        }
        __syncthreads();
#pragma unroll
        for (int kk = 0; kk < 16; kk++) {
            const ull* wr = &Wd[kk][ty * 4];
            ull a0 = wr[0], a1 = wr[1], a2 = wr[2], a3 = wr[3];
            const ull* xr = (const ull*)&Xs[kk][tx * 4];
            ull x01 = xr[0], x23 = xr[1];
            PFMA(acc[0][0], a0, x01, acc[0][0]); PFMA(acc[0][1], a0, x23, acc[0][1]);
            PFMA(acc[1][0], a1, x01, acc[1][0]); PFMA(acc[1][1], a1, x23, acc[1][1]);
            PFMA(acc[2][0], a2, x01, acc[2][0]); PFMA(acc[2][1], a2, x23, acc[2][1]);
            PFMA(acc[3][0], a3, x01, acc[3][0]); PFMA(acc[3][1], a3, x23, acc[3][1]);
        }
        __syncthreads();
    }
    float* Ob = g_proj + ((size_t)pid * Bn + bb) * Pp * Nn;
#pragma unroll
    for (int i = 0; i < 4; i++) {
        int p = ty * 4 + i;
        float bv = Bi[p];
        float4 r;
        r.x = __uint_as_float((uint)acc[i][0]) + bv;
        r.y = __uint_as_float((uint)(acc[i][0] >> 32)) + bv;
        r.z = __uint_as_float((uint)acc[i][1]) + bv;
        r.w = __uint_as_float((uint)(acc[i][1] >> 32)) + bv;
        *(float4*)(Ob + (size_t)p * Nn + n0 + tx * 4) = r;
    }
}

// ---------------- Flash attention on mma.sync (8 warps, double-buffered) ----------------
__global__ __launch_bounds__(256) void fa_mma_kernel() {
    __shared__ __align__(16) __nv_bfloat16 Qs[128][24];
    __shared__ __align__(16) __nv_bfloat16 KTs[2][16][136];
    __shared__ __align__(16) __nv_bfloat16 VTs[2][16][136];
    const int BUFB = 16 * 136 * 2;   // bytes per buffer

    int tid = threadIdx.x, lane = tid & 31, wid = tid >> 5;
    int it = blockIdx.x, z = blockIdx.y;
    int branch = z >> 4, bb = (z >> 2) & 3, h = z & 3;
    int i0 = it * 128;

    int qid = branch ? 3 : 0;
    int kid = branch ? 1 : 4;
    int vid = branch ? 2 : 5;
    const float* qb = g_proj + (((size_t)qid * Bn + bb) * Pp + h * Dd) * Nn;
    const float* kb = g_proj + (((size_t)kid * Bn + bb) * Pp + h * Dd) * Nn;
    const float* vb = g_proj + (((size_t)vid * Bn + bb) * Pp + h * Dd) * Nn;

    const float QS = 0.25f * 1.4426950408889634f;
    for (int idx = tid; idx < 2048; idx += 256) {
        int d = idx >> 7, m = idx & 127;
        Qs[m][d] = __float2bfloat16(qb[(size_t)d * Nn + i0 + m] * QS);
    }

    // per-thread tile-load slots
    int ld_d[4], ld_j[4];
#pragma unroll
    for (int r = 0; r < 4; r++) {
        int idx = tid + r * 256;
        ld_d[r] = idx >> 6;
        ld_j[r] = (idx & 63) * 2;
    }

    // preload tile 0 into buffer 0
#pragma unroll
    for (int r = 0; r < 4; r++) {
        float2 kv = *(const float2*)(kb + (size_t)ld_d[r] * Nn + ld_j[r]);
        float2 vv = *(const float2*)(vb + (size_t)ld_d[r] * Nn + ld_j[r]);
        uint kp, vp;
        asm("cvt.rn.bf16x2.f32 %0, %1, %2;" : "=r"(kp) : "f"(kv.y), "f"(kv.x));
        asm("cvt.rn.bf16x2.f32 %0, %1, %2;" : "=r"(vp) : "f"(vv.y), "f"(vv.x));
        *(uint*)&KTs[0][ld_d[r]][ld_j[r]] = kp;
        *(uint*)&VTs[0][ld_d[r]][ld_j[r]] = vp;
    }
    __syncthreads();

    uint qa[4];
    {
        int m0 = wid * 16;
        uint addr = smem_u32(&Qs[m0 + (lane & 15)][(lane >> 4) * 8]);
        LDSM_X4(qa[0], qa[1], qa[2], qa[3], addr);
    }

    float o[2][4] = {};
    ull rg2 = 0ull, rh2 = 0ull;

    uint kt_base = smem_u32(&KTs[0][lane & 15][0]);
    uint vt_base0 = smem_u32(&VTs[0][lane & 7][((lane >> 3) & 1) * 8]);
    uint vt_base1 = smem_u32(&VTs[0][8 + (lane & 7)][((lane >> 3) & 1) * 8]);

    for (int t = 0; t < 32; t++) {
        // prefetch next tile to regs (overlaps with compute below)
        float2 kpre[4], vpre[4];
        if (t < 31) {
            int j0n = (t + 1) * 128;
#pragma unroll
            for (int r = 0; r < 4; r++) {
                kpre[r] = *(const float2*)(kb + (size_t)ld_d[r] * Nn + j0n + ld_j[r]);
                vpre[r] = *(const float2*)(vb + (size_t)ld_d[r] * Nn + j0n + ld_j[r]);
            }
        }

        uint bo = (uint)(t & 1) * BUFB;
#pragma unroll
        for (int kc = 0; kc < 8; kc++) {
            int jb = kc * 16;
            uint kf0[2], kf1[2], vf0[2], vf1[2];
            LDSM_X2_T(kf0[0], kf0[1], kt_base + bo + jb * 2);
            LDSM_X2_T(kf1[0], kf1[1], kt_base + bo + jb * 2 + 16);
            LDSM_X2(vf0[0], vf0[1], vt_base0 + bo + jb * 2);
            LDSM_X2(vf1[0], vf1[1], vt_base1 + bo + jb * 2);

            float c0[4] = {0.f, 0.f, 0.f, 0.f};
            float c1[4] = {0.f, 0.f, 0.f, 0.f};
            mma16816(c0, qa, kf0);
            mma16816(c1, qa, kf1);
            ull p01 = pexp2(fpack(c0[0], c0[1]));
            ull p23 = pexp2(fpack(c0[2], c0[3]));
            ull q01 = pexp2(fpack(c1[0], c1[1]));
            ull q23 = pexp2(fpack(c1[2], c1[3]));
            PADD(rg2, rg2, p01);
            PADD(rg2, rg2, q01);
            PADD(rh2, rh2, p23);
            PADD(rh2, rh2, q23);
            uint pa[4];
            pa[0] = bfx2(p01);
            pa[1] = bfx2(p23);
            pa[2] = bfx2(q01);
            pa[3] = bfx2(q23);
            mma16816(o[0], pa, vf0);
            mma16816(o[1], pa, vf1);
        }

        if (t < 31) {
            int nb = (t + 1) & 1;
#pragma unroll
            for (int r = 0; r < 4; r++) {
                uint kp, vp;
                asm("cvt.rn.bf16x2.f32 %0, %1, %2;" : "=r"(kp) : "f"(kpre[r].y), "f"(kpre[r].x));
                asm("cvt.rn.bf16x2.f32 %0, %1, %2;" : "=r"(vp) : "f"(vpre[r].y), "f"(vpre[r].x));
                *(uint*)&KTs[nb][ld_d[r]][ld_j[r]] = kp;
                *(uint*)&VTs[nb][ld_d[r]][ld_j[r]] = vp;
            }
            __syncthreads();
        }
    }

    float* ob = g_attn + (((size_t)branch * Bn + bb) * Pp + h * Dd) * Nn;
    int g = lane >> 2, qd = lane & 3;
    int m0 = wid * 16;
    float lg = __uint_as_float((uint)rg2) + __uint_as_float((uint)(rg2 >> 32));
    float lh = __uint_as_float((uint)rh2) + __uint_as_float((uint)(rh2 >> 32));
    lg += __shfl_xor_sync(0xFFFFFFFFu, lg, 1);
    lg += __shfl_xor_sync(0xFFFFFFFFu, lg, 2);
    lh += __shfl_xor_sync(0xFFFFFFFFu, lh, 1);
    lh += __shfl_xor_sync(0xFFFFFFFFu, lh, 2);
    float ig = 1.f / lg, ih = 1.f / lh;
    int iq = i0 + m0 + g;
#pragma unroll
    for (int dt = 0; dt < 2; dt++) {
        int d = dt * 8 + qd * 2;
        ob[(size_t)d * Nn + iq]           = o[dt][0] * ig;
        ob[(size_t)(d + 1) * Nn + iq]     = o[dt][1] * ig;
        ob[(size_t)d * Nn + iq + 8]       = o[dt][2] * ih;
        ob[(size_t)(d + 1) * Nn + iq + 8] = o[dt][3] * ih;
    }
}

// ---------------- Output projection + residual + group partial sums ----------------
__global__ __launch_bounds__(256) void outproj_kernel(
    const float* __restrict__ fa, const float* __restrict__ fb,
    const float* __restrict__ owa, const float* __restrict__ oba,
    const float* __restrict__ owb, const float* __restrict__ obb,
    float* __restrict__ dout) {
    int z = blockIdx.z;
    int branch = z >> 2, bb = z & 3;
    int c0 = blockIdx.x * 64;
    int n0 = blockIdx.y * 64;
    const float* OW = branch ? owb : owa;
    const float* OB = branch ? obb : oba;
    const float* F  = (branch ? fb : fa) + (size_t)bb * Cc * Nn;
    const float* O  = g_attn + ((size_t)branch * Bn + bb) * Pp * Nn;

    __shared__ float OWs[64][65];
    __shared__ float Os[64][68];
    __shared__ float RS[16][17], RS2[16][17];

    int tid = threadIdx.x, tx = tid & 15, ty = tid >> 4;
#pragma unroll
    for (int r = 0; r < 4; r++) {
        int e = tid + r * 256;
        int cl = e >> 4;
        int p4 = (e & 15) << 2;
        float4 wv = *(const float4*)(OW + (size_t)(c0 + cl) * Pp + p4);
        OWs[p4 + 0][cl] = wv.x; OWs[p4 + 1][cl] = wv.y;
        OWs[p4 + 2][cl] = wv.z; OWs[p4 + 3][cl] = wv.w;
        int p = e >> 4;
        int nl = (e & 15) << 2;
        *(float4*)&Os[p][nl] = *(const float4*)(O + (size_t)p * Nn + n0 + nl);
    }
    __syncthreads();

    float acc[4][4] = {};
#pragma unroll 4
    for (int p = 0; p < 64; p++) {
        float a0 = OWs[p][ty * 4 + 0], a1 = OWs[p][ty * 4 + 1];
        float a2 = OWs[p][ty * 4 + 2], a3 = OWs[p][ty * 4 + 3];
        float4 xv = *(const float4*)&Os[p][tx * 4];
        acc[0][0] = fmaf(a0, xv.x, acc[0][0]); acc[0][1] = fmaf(a0, xv.y, acc[0][1]);
        acc[0][2] = fmaf(a0, xv.z, acc[0][2]); acc[0][3] = fmaf(a0, xv.w, acc[0][3]);
        acc[1][0] = fmaf(a1, xv.x, acc[1][0]); acc[1][1] = fmaf(a1, xv.y, acc[1][1]);
        acc[1][2] = fmaf(a1, xv.z, acc[1][2]); acc[1][3] = fmaf(a1, xv.w, acc[1][3]);
        acc[2][0] = fmaf(a2, xv.x, acc[2][0]); acc[2][1] = fmaf(a2, xv.y, acc[2][1]);
        acc[2][2] = fmaf(a2, xv.z, acc[2][2]); acc[2][3] = fmaf(a2, xv.w, acc[2][3]);
        acc[3][0] = fmaf(a3, xv.x, acc[3][0]); acc[3][1] = fmaf(a3, xv.y, acc[3][1]);
        acc[3][2] = fmaf(a3, xv.z, acc[3][2]); acc[3][3] = fmaf(a3, xv.w, acc[3][3]);
    }
    size_t obase = (size_t)branch * Bn * Cc * Nn + (size_t)bb * Cc * Nn;
    float ls = 0.f, ls2 = 0.f;
#pragma unroll
    for (int i = 0; i < 4; i++) {
        int c = c0 + ty * 4 + i;
        float bv = OB[c];
        float4 fv = *(const float4*)(F + (size_t)c * Nn + n0 + tx * 4);
        float4 r = make_float4(acc[i][0] + bv + fv.x, acc[i][1] + bv + fv.y,
                               acc[i][2] + bv + fv.z, acc[i][3] + bv + fv.w);
        ls  += r.x + r.y + r.z + r.w;
        ls2 += r.x * r.x + r.y * r.y + r.z * r.z + r.w * r.w;
        *(float4*)(dout + obase + (size_t)c * Nn + n0 + tx * 4) = r;
    }

    // per-group partial sums: thread's 4 c-rows all lie in group gl = ty>>2
    RS[ty][tx] = ls;
    RS2[ty][tx] = ls2;
    __syncthreads();
    if (tid < 64) {
        int gl = tid >> 4, cc = tid & 15;
        float s  = RS[gl * 4 + 0][cc] + RS[gl * 4 + 1][cc] + RS[gl * 4 + 2][cc] + RS[gl * 4 + 3][cc];
        float s2 = RS2[gl * 4 + 0][cc] + RS2[gl * 4 + 1][cc] + RS2[gl * 4 + 2][cc] + RS2[gl * 4 + 3][cc];
#pragma unroll
        for (int st = 8; st > 0; st >>= 1) {
            s  += __shfl_xor_sync(0xFFFFFFFFu, s, st);
            s2 += __shfl_xor_sync(0xFFFFFFFFu, s2, st);
        }
        if (cc == 0) {
            int gidx = blockIdx.x * 4 + gl;            // group 0..15
            float* pp = g_part + (((size_t)z * 16 + gidx) * 64 + blockIdx.y) * 2;
            pp[0] = s;
            pp[1] = s2;
        }
    }
}

// ---------------- final stats: reduce 64 partials per (z,group) ----------------
__global__ __launch_bounds__(64) void stats_final_kernel() {
    int gidx = blockIdx.x;     // z*16+g
    int tid = threadIdx.x;
    const float* pp = g_part + ((size_t)gidx * 64 + tid) * 2;
    float s = pp[0], s2 = pp[1];
#pragma unroll
    for (int st = 16; st > 0; st >>= 1) {
        s  += __shfl_xor_sync(0xFFFFFFFFu, s, st);
        s2 += __shfl_xor_sync(0xFFFFFFFFu, s2, st);
    }
    __shared__ float sh[2], sh2[2];
    if ((tid & 31) == 0) { sh[tid >> 5] = s; sh2[tid >> 5] = s2; }
    __syncthreads();
    if (tid == 0) {
        float S = sh[0] + sh[1], S2 = sh2[0] + sh2[1];
        float mean = S * (1.f / 65536.f);
        float var  = S2 * (1.f / 65536.f) - mean * mean;
        g_stats[gidx * 2 + 0] = mean;
        g_stats[gidx * 2 + 1] = rsqrtf(var + 1e-5f);
    }
}

// ---------------- Normalize in place ----------------
__global__ __launch_bounds__(256) void norm_kernel(float* __restrict__ dout,
                                                   const float* __restrict__ ga, const float* __restrict__ bta,
                                                   const float* __restrict__ gb, const float* __restrict__ btb) {
    size_t qi = (size_t)blockIdx.x * blockDim.x + threadIdx.x;
    if (qi >= (size_t)2 * Bn * Cc * Nn / 4) return;
    size_t e = qi * 4;
    int branch = (int)(e >> 22);
    size_t r = e & ((1ull << 22) - 1);
    int c = (int)((r >> 12) & 255);
    int bb = (int)(r >> 20);
    int g = c >> 4;
    int sidx = (branch * 4 + bb) * 16 + g;
    float mean = g_stats[sidx * 2 + 0];
    float rstd = g_stats[sidx * 2 + 1];
    float gamma = (branch ? gb : ga)[c];
    float beta  = (branch ? btb : bta)[c];
    float aa = rstd * gamma;
    float bc = beta - mean * aa;
    float4 v = *(float4*)(dout + e);
    v.x = fmaf(v.x, aa, bc); v.y = fmaf(v.y, aa, bc);
    v.z = fmaf(v.z, aa, bc); v.w = fmaf(v.w, aa, bc);
    *(float4*)(dout + e) = v;
}

extern "C" void kernel_launch(void* const* d_in, const int* in_sizes, int n_in,
                              void* d_out, int out_size) {
    const float* feat_a = (const float*)d_in[0];
    const float* feat_b = (const float*)d_in[1];

    ProjArgs pa;
    pa.x[0] = feat_a; pa.x[1] = feat_b;
    pa.w[0] = (const float*)d_in[2];  pa.b[0] = (const float*)d_in[3];   // q_a
    pa.w[1] = (const float*)d_in[10]; pa.b[1] = (const float*)d_in[11];  // k_a
    pa.w[2] = (const float*)d_in[12]; pa.b[2] = (const float*)d_in[13];  // v_a
    pa.w[3] = (const float*)d_in[8];  pa.b[3] = (const float*)d_in[9];   // q_b
    pa.w[4] = (const float*)d_in[4];  pa.b[4] = (const float*)d_in[5];   // k_b
    pa.w[5] = (const float*)d_in[6];  pa.b[5] = (const float*)d_in[7];   // v_b

    float* dout = (float*)d_out;

    dim3 pg(Nn / 64, Bn, 6);
    proj_kernel<<<pg, 256>>>(pa);

    dim3 fg(Nn / 128, 2 * Bn * Hh);
    fa_mma_kernel<<<fg, 256>>>();

    dim3 og(Cc / 64, Nn / 64, 2 * Bn);
    outproj_kernel<<<og, 256>>>(feat_a, feat_b,
                                (const float*)d_in[14], (const float*)d_in[15],
                                (const float*)d_in[16], (const float*)d_in[17],
                                dout);

    stats_final_kernel<<<128, 64>>>();

    size_t nvec = (size_t)2 * Bn * Cc * Nn / 4;
    norm_kernel<<<(unsigned)((nvec + 255) / 256), 256>>>(dout,
                                (const float*)d_in[18], (const float*)d_in[19],
                                (const float*)d_in[20], (const float*)d_in[21]);
}

// round 8
// speedup vs baseline: 1.1134x; 1.1134x over previous
#include <cuda_runtime.h>
#include <cuda_bf16.h>

#define Bn 4
#define Cc 256
#define Pp 64
#define Hh 4
#define Dd 16
#define Nn 4096

typedef unsigned long long ull;
typedef unsigned int uint;

// Scratch (device globals; no allocation allowed)
__device__ float g_proj[6 * Bn * Pp * Nn];   // [proj_id][b][p][n]
__device__ float g_attn[2 * Bn * Pp * Nn];   // [branch][b][p][n]
__device__ float g_part[8 * 16 * 64 * 2];    // per (z,group,ntile): s, s2
__device__ float g_stats[2 * Bn * 16 * 2];   // mean, rstd per (branch,b,group)

struct ProjArgs {
    const float* x[2];
    const float* w[6];
    const float* b[6];
};

// ---- packed f32x2 ops (FMA pipe) ----
#define PFMA(d, a, b, c) asm("fma.rn.f32x2 %0,%1,%2,%3;" : "=l"(d) : "l"(a), "l"(b), "l"(c))
#define PADD(d, a, b)    asm("add.rn.f32x2 %0,%1,%2;"    : "=l"(d) : "l"(a), "l"(b))

__device__ __forceinline__ ull fdup(float x) {
    uint u = __float_as_uint(x);
    return ((ull)u << 32) | u;
}
__device__ __forceinline__ ull fpack(float lo, float hi) {
    return ((ull)__float_as_uint(hi) << 32) | __float_as_uint(lo);
}

// packed 2^t: round trick + degree-3 Taylor + exponent splice.
// |abs err| < 7e-4 relative — below the bf16 quantization applied to P.
__device__ __forceinline__ ull pexp2(ull t) {
    ull r, fi, f, p;
    PADD(r, t, fdup(12582912.f));
    PADD(fi, r, fdup(-12582912.f));
    PFMA(f, fi, fdup(-1.f), t);
    p = fdup(5.55041087e-2f);
    PFMA(p, p, f, fdup(2.40226507e-1f));
    PFMA(p, p, f, fdup(6.93147181e-1f));
    PFMA(p, p, f, fdup(1.0f));
    uint lo = (uint)p + ((uint)r << 23);
    uint hi = (uint)(p >> 32) + ((uint)(r >> 32) << 23);
    return ((ull)hi << 32) | lo;
}

__device__ __forceinline__ uint smem_u32(const void* p) {
    uint a;
    asm("{ .reg .u64 t; cvta.to.shared.u64 t, %1; cvt.u32.u64 %0, t; }" : "=r"(a) : "l"(p));
    return a;
}

__device__ __forceinline__ uint bfx2(ull p) {
    float lo = __uint_as_float((uint)p);
    float hi = __uint_as_float((uint)(p >> 32));
    uint r;
    asm("cvt.rn.bf16x2.f32 %0, %1, %2;" : "=r"(r) : "f"(hi), "f"(lo));
    return r;
}

#define LDSM_X4(r0, r1, r2, r3, a) \
    asm volatile("ldmatrix.sync.aligned.m8n8.x4.shared.b16 {%0,%1,%2,%3}, [%4];" \
        : "=r"(r0), "=r"(r1), "=r"(r2), "=r"(r3) : "r"(a))
#define LDSM_X2(r0, r1, a) \
    asm volatile("ldmatrix.sync.aligned.m8n8.x2.shared.b16 {%0,%1}, [%2];" \
        : "=r"(r0), "=r"(r1) : "r"(a))
#define LDSM_X2_T(r0, r1, a) \
    asm volatile("ldmatrix.sync.aligned.m8n8.x2.trans.shared.b16 {%0,%1}, [%2];" \
        : "=r"(r0), "=r"(r1) : "r"(a))

__device__ __forceinline__ void mma16816(float* c, const uint* a, const uint* b) {
    asm volatile(
        "mma.sync.aligned.m16n8k16.row.col.f32.bf16.bf16.f32 "
        "{%0,%1,%2,%3}, {%4,%5,%6,%7}, {%8,%9}, {%0,%1,%2,%3};"
        : "+f"(c[0]), "+f"(c[1]), "+f"(c[2]), "+f"(c[3])
        : "r"(a[0]), "r"(a[1]), "r"(a[2]), "r"(a[3]), "r"(b[0]), "r"(b[1]));
}

// ---------------- QKV projection (packed f32x2 inner loop) ----------------
__global__ __launch_bounds__(256) void proj_kernel(ProjArgs a) {
    int pid = blockIdx.z;
    int bb  = blockIdx.y;
    int n0  = blockIdx.x * 64;
    const float* X  = a.x[pid >= 3 ? 1 : 0] + (size_t)bb * Cc * Nn;
    const float* W  = a.w[pid];
    const float* Bi = a.b[pid];

    __shared__ __align__(16) ull  Wd[16][68];   // padded: rows 544B (16B aligned)
    __shared__ __align__(16) float Xs[16][68];

    int tid = threadIdx.x;
    int tx = tid & 15, ty = tid >> 4;
    ull acc[4][2] = {};

    for (int k0 = 0; k0 < Cc; k0 += 16) {
        {
            int p  = tid >> 2;
            int cc = (tid & 3) << 2;
            float4 wv = *(const float4*)(W + (size_t)p * Cc + k0 + cc);
            Wd[cc + 0][p] = fdup(wv.x); Wd[cc + 1][p] = fdup(wv.y);
            Wd[cc + 2][p] = fdup(wv.z); Wd[cc + 3][p] = fdup(wv.w);
        }
        {
            int kk = ty;
            int nn = tx << 2;
            *(float4*)&Xs[kk][nn] = *(const float4*)(X + (size_t)(k0 + kk) * Nn + n0 + nn);
        }
        __syncthreads();
#pragma unroll
        for (int kk = 0; kk < 16; kk++) {
            const ulonglong2* wr = (const ulonglong2*)&Wd[kk][ty * 4];
            ulonglong2 w01 = wr[0], w23 = wr[1];
            const ull* xr = (const ull*)&Xs[kk][tx * 4];
            ull x01 = xr[0], x23 = xr[1];
            PFMA(acc[0][0], w01.x, x01, acc[0][0]); PFMA(acc[0][1], w01.x, x23, acc[0][1]);
            PFMA(acc[1][0], w01.y, x01, acc[1][0]); PFMA(acc[1][1], w01.y, x23, acc[1][1]);
            PFMA(acc[2][0], w23.x, x01, acc[2][0]); PFMA(acc[2][1], w23.x, x23, acc[2][1]);
            PFMA(acc[3][0], w23.y, x01, acc[3][0]); PFMA(acc[3][1], w23.y, x23, acc[3][1]);
        }
        __syncthreads();
    }
    float* Ob = g_proj + ((size_t)pid * Bn + bb) * Pp * Nn;
#pragma unroll
    for (int i = 0; i < 4; i++) {
        int p = ty * 4 + i;
        float bv = Bi[p];
        float4 r;
        r.x = __uint_as_float((uint)acc[i][0]) + bv;
        r.y = __uint_as_float((uint)(acc[i][0] >> 32)) + bv;
        r.z = __uint_as_float((uint)acc[i][1]) + bv;
        r.w = __uint_as_float((uint)(acc[i][1] >> 32)) + bv;
        *(float4*)(Ob + (size_t)p * Nn + n0 + tx * 4) = r;
    }
}

// ---------------- Flash attention on mma.sync (8 warps; tensor-core row sums) ----------------
__global__ __launch_bounds__(256) void fa_mma_kernel() {
    __shared__ __align__(16) __nv_bfloat16 Qs[128][24];
    __shared__ __align__(16) __nv_bfloat16 KTs[16][136];
    __shared__ __align__(16) __nv_bfloat16 VTs[16][136];

    int tid = threadIdx.x, lane = tid & 31, wid = tid >> 5;
    int it = blockIdx.x, z = blockIdx.y;
    int branch = z >> 4, bb = (z >> 2) & 3, h = z & 3;
    int i0 = it * 128;

    int qid = branch ? 3 : 0;
    int kid = branch ? 1 : 4;
    int vid = branch ? 2 : 5;
    const float* qb = g_proj + (((size_t)qid * Bn + bb) * Pp + h * Dd) * Nn;
    const float* kb = g_proj + (((size_t)kid * Bn + bb) * Pp + h * Dd) * Nn;
    const float* vb = g_proj + (((size_t)vid * Bn + bb) * Pp + h * Dd) * Nn;

    const float QS = 0.25f * 1.4426950408889634f;
    for (int idx = tid; idx < 2048; idx += 256) {
        int d = idx >> 7, m = idx & 127;
        Qs[m][d] = __float2bfloat16(qb[(size_t)d * Nn + i0 + m] * QS);
    }
    __syncthreads();

    uint qa[4];
    {
        int m0 = wid * 16;
        uint addr = smem_u32(&Qs[m0 + (lane & 15)][(lane >> 4) * 8]);
        LDSM_X4(qa[0], qa[1], qa[2], qa[3], addr);
    }

    float o[2][4] = {};
    float o2[4] = {};                       // tensor-core row sums (ones column)
    const uint ones[2] = {0x3F803F80u, 0x3F803F80u};

    uint kt_base = smem_u32(&KTs[lane & 15][0]);
    uint vt_base0 = smem_u32(&VTs[lane & 7][((lane >> 3) & 1) * 8]);
    uint vt_base1 = smem_u32(&VTs[8 + (lane & 7)][((lane >> 3) & 1) * 8]);

    int ld_d[4], ld_j[4];
#pragma unroll
    for (int r = 0; r < 4; r++) {
        int idx = tid + r * 256;
        ld_d[r] = idx >> 6;
        ld_j[r] = (idx & 63) * 2;
    }

    float2 kpre[4], vpre[4];
#pragma unroll
    for (int r = 0; r < 4; r++) {
        kpre[r] = *(const float2*)(kb + (size_t)ld_d[r] * Nn + ld_j[r]);
        vpre[r] = *(const float2*)(vb + (size_t)ld_d[r] * Nn + ld_j[r]);
    }

    for (int t = 0; t < 32; t++) {
        __syncthreads();
#pragma unroll
        for (int r = 0; r < 4; r++) {
            uint kp, vp;
            asm("cvt.rn.bf16x2.f32 %0, %1, %2;" : "=r"(kp) : "f"(kpre[r].y), "f"(kpre[r].x));
            asm("cvt.rn.bf16x2.f32 %0, %1, %2;" : "=r"(vp) : "f"(vpre[r].y), "f"(vpre[r].x));
            *(uint*)&KTs[ld_d[r]][ld_j[r]] = kp;
            *(uint*)&VTs[ld_d[r]][ld_j[r]] = vp;
        }
        __syncthreads();

        if (t < 31) {
            int j0n = (t + 1) * 128;
#pragma unroll
            for (int r = 0; r < 4; r++) {
                kpre[r] = *(const float2*)(kb + (size_t)ld_d[r] * Nn + j0n + ld_j[r]);
                vpre[r] = *(const float2*)(vb + (size_t)ld_d[r] * Nn + j0n + ld_j[r]);
            }
        }

#pragma unroll
        for (int kc = 0; kc < 8; kc++) {
            int jb = kc * 16;
            uint kf0[2], kf1[2], vf0[2], vf1[2];
            LDSM_X2_T(kf0[0], kf0[1], kt_base + jb * 2);
            LDSM_X2_T(kf1[0], kf1[1], kt_base + jb * 2 + 16);
            LDSM_X2(vf0[0], vf0[1], vt_base0 + jb * 2);
            LDSM_X2(vf1[0], vf1[1], vt_base1 + jb * 2);

            float c0[4] = {0.f, 0.f, 0.f, 0.f};
            float c1[4] = {0.f, 0.f, 0.f, 0.f};
            mma16816(c0, qa, kf0);
            mma16816(c1, qa, kf1);
            ull p01 = pexp2(fpack(c0[0], c0[1]));
            ull p23 = pexp2(fpack(c0[2], c0[3]));
            ull q01 = pexp2(fpack(c1[0], c1[1]));
            ull q23 = pexp2(fpack(c1[2], c1[3]));
            uint pa[4];
            pa[0] = bfx2(p01);
            pa[1] = bfx2(p23);
            pa[2] = bfx2(q01);
            pa[3] = bfx2(q23);
            mma16816(o[0], pa, vf0);
            mma16816(o[1], pa, vf1);
            mma16816(o2, pa, ones);      // row sums on tensor pipe
        }
    }

    float* ob = g_attn + (((size_t)branch * Bn + bb) * Pp + h * Dd) * Nn;
    int g = lane >> 2, qd = lane & 3;
    int m0 = wid * 16;
    float ig = 1.f / o2[0];              // rows g   (all cols of ones tile equal)
    float ih = 1.f / o2[2];              // rows g+8
    int iq = i0 + m0 + g;
#pragma unroll
    for (int dt = 0; dt < 2; dt++) {
        int d = dt * 8 + qd * 2;
        ob[(size_t)d * Nn + iq]           = o[dt][0] * ig;
        ob[(size_t)(d + 1) * Nn + iq]     = o[dt][1] * ig;
        ob[(size_t)d * Nn + iq + 8]       = o[dt][2] * ih;
        ob[(size_t)(d + 1) * Nn + iq + 8] = o[dt][3] * ih;
    }
}

// ---------------- Output projection + residual + group partial sums ----------------
__global__ __launch_bounds__(256) void outproj_kernel(
    const float* __restrict__ fa, const float* __restrict__ fb,
    const float* __restrict__ owa, const float* __restrict__ oba,
    const float* __restrict__ owb, const float* __restrict__ obb,
    float* __restrict__ dout) {
    int z = blockIdx.z;
    int branch = z >> 2, bb = z & 3;
    int c0 = blockIdx.x * 64;
    int n0 = blockIdx.y * 64;
    const float* OW = branch ? owb : owa;
    const float* OB = branch ? obb : oba;
    const float* F  = (branch ? fb : fa) + (size_t)bb * Cc * Nn;
    const float* O  = g_attn + ((size_t)branch * Bn + bb) * Pp * Nn;

    __shared__ float OWs[64][65];
    __shared__ float Os[64][68];
    __shared__ float RS[16][17], RS2[16][17];

    int tid = threadIdx.x, tx = tid & 15, ty = tid >> 4;
#pragma unroll
    for (int r = 0; r < 4; r++) {
        int e = tid + r * 256;
        int cl = e >> 4;
        int p4 = (e & 15) << 2;
        float4 wv = *(const float4*)(OW + (size_t)(c0 + cl) * Pp + p4);
        OWs[p4 + 0][cl] = wv.x; OWs[p4 + 1][cl] = wv.y;
        OWs[p4 + 2][cl] = wv.z; OWs[p4 + 3][cl] = wv.w;
        int p = e >> 4;
        int nl = (e & 15) << 2;
        *(float4*)&Os[p][nl] = *(const float4*)(O + (size_t)p * Nn + n0 + nl);
    }
    __syncthreads();

    float acc[4][4] = {};
#pragma unroll 4
    for (int p = 0; p < 64; p++) {
        float a0 = OWs[p][ty * 4 + 0], a1 = OWs[p][ty * 4 + 1];
        float a2 = OWs[p][ty * 4 + 2], a3 = OWs[p][ty * 4 + 3];
        float4 xv = *(const float4*)&Os[p][tx * 4];
        acc[0][0] = fmaf(a0, xv.x, acc[0][0]); acc[0][1] = fmaf(a0, xv.y, acc[0][1]);
        acc[0][2] = fmaf(a0, xv.z, acc[0][2]); acc[0][3] = fmaf(a0, xv.w, acc[0][3]);
        acc[1][0] = fmaf(a1, xv.x, acc[1][0]); acc[1][1] = fmaf(a1, xv.y, acc[1][1]);
        acc[1][2] = fmaf(a1, xv.z, acc[1][2]); acc[1][3] = fmaf(a1, xv.w, acc[1][3]);
        acc[2][0] = fmaf(a2, xv.x, acc[2][0]); acc[2][1] = fmaf(a2, xv.y, acc[2][1]);
        acc[2][2] = fmaf(a2, xv.z, acc[2][2]); acc[2][3] = fmaf(a2, xv.w, acc[2][3]);
        acc[3][0] = fmaf(a3, xv.x, acc[3][0]); acc[3][1] = fmaf(a3, xv.y, acc[3][1]);
        acc[3][2] = fmaf(a3, xv.z, acc[3][2]); acc[3][3] = fmaf(a3, xv.w, acc[3][3]);
    }
    size_t obase = (size_t)branch * Bn * Cc * Nn + (size_t)bb * Cc * Nn;
    float ls = 0.f, ls2 = 0.f;
#pragma unroll
    for (int i = 0; i < 4; i++) {
        int c = c0 + ty * 4 + i;
        float bv = OB[c];
        float4 fv = *(const float4*)(F + (size_t)c * Nn + n0 + tx * 4);
        float4 r = make_float4(acc[i][0] + bv + fv.x, acc[i][1] + bv + fv.y,
                               acc[i][2] + bv + fv.z, acc[i][3] + bv + fv.w);
        ls  += r.x + r.y + r.z + r.w;
        ls2 += r.x * r.x + r.y * r.y + r.z * r.z + r.w * r.w;
        *(float4*)(dout + obase + (size_t)c * Nn + n0 + tx * 4) = r;
    }

    RS[ty][tx] = ls;
    RS2[ty][tx] = ls2;
    __syncthreads();
    if (tid < 64) {
        int gl = tid >> 4, cc = tid & 15;
        float s  = RS[gl * 4 + 0][cc] + RS[gl * 4 + 1][cc] + RS[gl * 4 + 2][cc] + RS[gl * 4 + 3][cc];
        float s2 = RS2[gl * 4 + 0][cc] + RS2[gl * 4 + 1][cc] + RS2[gl * 4 + 2][cc] + RS2[gl * 4 + 3][cc];
#pragma unroll
        for (int st = 8; st > 0; st >>= 1) {
            s  += __shfl_xor_sync(0xFFFFFFFFu, s, st);
            s2 += __shfl_xor_sync(0xFFFFFFFFu, s2, st);
        }
        if (cc == 0) {
            int gidx = blockIdx.x * 4 + gl;
            float* pp = g_part + (((size_t)z * 16 + gidx) * 64 + blockIdx.y) * 2;
            pp[0] = s;
            pp[1] = s2;
        }
    }
}

// ---------------- final stats ----------------
__global__ __launch_bounds__(64) void stats_final_kernel() {
    int gidx = blockIdx.x;
    int tid = threadIdx.x;
    const float* pp = g_part + ((size_t)gidx * 64 + tid) * 2;
    float s = pp[0], s2 = pp[1];
#pragma unroll
    for (int st = 16; st > 0; st >>= 1) {
        s  += __shfl_xor_sync(0xFFFFFFFFu, s, st);
        s2 += __shfl_xor_sync(0xFFFFFFFFu, s2, st);
    }
    __shared__ float sh[2], sh2[2];
    if ((tid & 31) == 0) { sh[tid >> 5] = s; sh2[tid >> 5] = s2; }
    __syncthreads();
    if (tid == 0) {
        float S = sh[0] + sh[1], S2 = sh2[0] + sh2[1];
        float mean = S * (1.f / 65536.f);
        float var  = S2 * (1.f / 65536.f) - mean * mean;
        g_stats[gidx * 2 + 0] = mean;
        g_stats[gidx * 2 + 1] = rsqrtf(var + 1e-5f);
    }
}

// ---------------- Normalize in place ----------------
__global__ __launch_bounds__(256) void norm_kernel(float* __restrict__ dout,
                                                   const float* __restrict__ ga, const float* __restrict__ bta,
                                                   const float* __restrict__ gb, const float* __restrict__ btb) {
    size_t qi = (size_t)blockIdx.x * blockDim.x + threadIdx.x;
    if (qi >= (size_t)2 * Bn * Cc * Nn / 4) return;
    size_t e = qi * 4;
    int branch = (int)(e >> 22);
    size_t r = e & ((1ull << 22) - 1);
    int c = (int)((r >> 12) & 255);
    int bb = (int)(r >> 20);
    int g = c >> 4;
    int sidx = (branch * 4 + bb) * 16 + g;
    float mean = g_stats[sidx * 2 + 0];
    float rstd = g_stats[sidx * 2 + 1];
    float gamma = (branch ? gb : ga)[c];
    float beta  = (branch ? btb : bta)[c];
    float aa = rstd * gamma;
    float bc = beta - mean * aa;
    float4 v = *(float4*)(dout + e);
    v.x = fmaf(v.x, aa, bc); v.y = fmaf(v.y, aa, bc);
    v.z = fmaf(v.z, aa, bc); v.w = fmaf(v.w, aa, bc);
    *(float4*)(dout + e) = v;
}

extern "C" void kernel_launch(void* const* d_in, const int* in_sizes, int n_in,
                              void* d_out, int out_size) {
    const float* feat_a = (const float*)d_in[0];
    const float* feat_b = (const float*)d_in[1];

    ProjArgs pa;
    pa.x[0] = feat_a; pa.x[1] = feat_b;
    pa.w[0] = (const float*)d_in[2];  pa.b[0] = (const float*)d_in[3];   // q_a
    pa.w[1] = (const float*)d_in[10]; pa.b[1] = (const float*)d_in[11];  // k_a
    pa.w[2] = (const float*)d_in[12]; pa.b[2] = (const float*)d_in[13];  // v_a
    pa.w[3] = (const float*)d_in[8];  pa.b[3] = (const float*)d_in[9];   // q_b
    pa.w[4] = (const float*)d_in[4];  pa.b[4] = (const float*)d_in[5];   // k_b
    pa.w[5] = (const float*)d_in[6];  pa.b[5] = (const float*)d_in[7];   // v_b

    float* dout = (float*)d_out;

    dim3 pg(Nn / 64, Bn, 6);
    proj_kernel<<<pg, 256>>>(pa);

    dim3 fg(Nn / 128, 2 * Bn * Hh);
    fa_mma_kernel<<<fg, 256>>>();

    dim3 og(Cc / 64, Nn / 64, 2 * Bn);
    outproj_kernel<<<og, 256>>>(feat_a, feat_b,
                                (const float*)d_in[14], (const float*)d_in[15],
                                (const float*)d_in[16], (const float*)d_in[17],
                                dout);

    stats_final_kernel<<<128, 64>>>();

    size_t nvec = (size_t)2 * Bn * Cc * Nn / 4;
    norm_kernel<<<(unsigned)((nvec + 255) / 256), 256>>>(dout,
                                (const float*)d_in[18], (const float*)d_in[19],
                                (const float*)d_in[20], (const float*)d_in[21]);
}

// round 9
// speedup vs baseline: 1.4293x; 1.2836x over previous
#include <cuda_runtime.h>
#include <cuda_bf16.h>

#define Bn 4
#define Cc 256
#define Pp 64
#define Hh 4
#define Dd 16
#define Nn 4096

typedef unsigned long long ull;
typedef unsigned int uint;
typedef unsigned short ushort_t;

// Scratch (device globals; no allocation allowed)
__device__ __nv_bfloat16 g_projh[6 * Bn * Pp * Nn];  // [pid][b][p][n] bf16; q pre-scaled
__device__ float g_attn[2 * Bn * Pp * Nn];           // [branch][b][p][n]
__device__ float g_part[8 * 16 * 64 * 2];            // per (z,group,ntile): s, s2
__device__ float g_stats[2 * Bn * 16 * 2];           // mean, rstd

struct ProjArgs {
    const float* x[2];
    const float* w[6];
    const float* b[6];
};

// ---- packed f32x2 ops (FMA pipe) ----
#define PFMA(d, a, b, c) asm("fma.rn.f32x2 %0,%1,%2,%3;" : "=l"(d) : "l"(a), "l"(b), "l"(c))
#define PADD(d, a, b)    asm("add.rn.f32x2 %0,%1,%2;"    : "=l"(d) : "l"(a), "l"(b))

__device__ __forceinline__ ull fdup(float x) {
    uint u = __float_as_uint(x);
    return ((ull)u << 32) | u;
}
__device__ __forceinline__ ull fpack(float lo, float hi) {
    return ((ull)__float_as_uint(hi) << 32) | __float_as_uint(lo);
}

// packed 2^t: round trick + degree-3 Taylor + exponent splice.
__device__ __forceinline__ ull pexp2(ull t) {
    ull r, fi, f, p;
    PADD(r, t, fdup(12582912.f));
    PADD(fi, r, fdup(-12582912.f));
    PFMA(f, fi, fdup(-1.f), t);
    p = fdup(5.55041087e-2f);
    PFMA(p, p, f, fdup(2.40226507e-1f));
    PFMA(p, p, f, fdup(6.93147181e-1f));
    PFMA(p, p, f, fdup(1.0f));
    uint lo = (uint)p + ((uint)r << 23);
    uint hi = (uint)(p >> 32) + ((uint)(r >> 32) << 23);
    return ((ull)hi << 32) | lo;
}

__device__ __forceinline__ uint smem_u32(const void* p) {
    uint a;
    asm("{ .reg .u64 t; cvta.to.shared.u64 t, %1; cvt.u32.u64 %0, t; }" : "=r"(a) : "l"(p));
    return a;
}

__device__ __forceinline__ uint bfx2(ull p) {
    float lo = __uint_as_float((uint)p);
    float hi = __uint_as_float((uint)(p >> 32));
    uint r;
    asm("cvt.rn.bf16x2.f32 %0, %1, %2;" : "=r"(r) : "f"(hi), "f"(lo));
    return r;
}

#define LDSM_X4(r0, r1, r2, r3, a) \
    asm volatile("ldmatrix.sync.aligned.m8n8.x4.shared.b16 {%0,%1,%2,%3}, [%4];" \
        : "=r"(r0), "=r"(r1), "=r"(r2), "=r"(r3) : "r"(a))
#define LDSM_X2(r0, r1, a) \
    asm volatile("ldmatrix.sync.aligned.m8n8.x2.shared.b16 {%0,%1}, [%2];" \
        : "=r"(r0), "=r"(r1) : "r"(a))
#define LDSM_X2_T(r0, r1, a) \
    asm volatile("ldmatrix.sync.aligned.m8n8.x2.trans.shared.b16 {%0,%1}, [%2];" \
        : "=r"(r0), "=r"(r1) : "r"(a))

__device__ __forceinline__ void mma16816(float* c, const uint* a, const uint* b) {
    asm volatile(
        "mma.sync.aligned.m16n8k16.row.col.f32.bf16.bf16.f32 "
        "{%0,%1,%2,%3}, {%4,%5,%6,%7}, {%8,%9}, {%0,%1,%2,%3};"
        : "+f"(c[0]), "+f"(c[1]), "+f"(c[2]), "+f"(c[3])
        : "r"(a[0]), "r"(a[1]), "r"(a[2]), "r"(a[3]), "r"(b[0]), "r"(b[1]));
}

// ---------------- QKV projection on tensor cores ----------------
// CTA = (src, batch, 64-wide n tile). 12 warps; warp w = m16 tile of M=192
// (rows 0-63: q [QS-scaled], 64-127: k, 128-191: v). K=256 in 8 slabs of 32.
__global__ __launch_bounds__(384) void proj_mma_kernel(ProjArgs a) {
    __shared__ __align__(16) __nv_bfloat16 Wt[192][40];  // [m][k-slab], pad 40
    __shared__ __align__(16) __nv_bfloat16 Xs[32][72];   // [k][n], pad 72

    int tid = threadIdx.x, lane = tid & 31, wid = tid >> 5;
    int n0 = blockIdx.x * 64;
    int bb = blockIdx.y;
    int src = blockIdx.z;
    const float* X = a.x[src] + (size_t)bb * Cc * Nn;
    const float QS = 0.25f * 1.4426950408889634f;

    int m0 = wid * 16;
    int pid_l = m0 >> 6;            // 0=q,1=k,2=v for this warp

    float c[8][4] = {};
    uint xs_b0 = smem_u32(&Xs[lane & 15][0]);
    uint xs_b1 = smem_u32(&Xs[16 + (lane & 15)][0]);

    for (int s8 = 0; s8 < 8; s8++) {
        int k0 = s8 * 32;
        __syncthreads();
        // W slab: 192 rows x 32 cols; 1536 float4 loads
#pragma unroll
        for (int r = 0; r < 4; r++) {
            int e = tid + r * 384;
            int m = e >> 3;
            int cc4 = (e & 7) << 2;
            int wsel = m >> 6;
            int p = m & 63;
            float4 wv = *(const float4*)(a.w[src * 3 + wsel] + (size_t)p * Cc + k0 + cc4);
            if (wsel == 0) { wv.x *= QS; wv.y *= QS; wv.z *= QS; wv.w *= QS; }
            uint* wr = (uint*)&Wt[m][cc4];
            wr[0] = bfx2(fpack(wv.x, wv.y));
            wr[1] = bfx2(fpack(wv.z, wv.w));
        }
        // X slab: 32 k x 64 n
        for (int s = tid; s < 1024; s += 384) {
            int k = s >> 5;
            int n2 = (s & 31) << 1;
            float2 xv = *(const float2*)(X + (size_t)(k0 + k) * Nn + n0 + n2);
            *(uint*)&Xs[k][n2] = bfx2(fpack(xv.x, xv.y));
        }
        __syncthreads();

#pragma unroll
        for (int ks = 0; ks < 2; ks++) {
            uint wa[4];
            uint aaddr = smem_u32(&Wt[m0 + (lane & 15)][ks * 16 + (lane >> 4) * 8]);
            LDSM_X4(wa[0], wa[1], wa[2], wa[3], aaddr);
            uint xsb = ks ? xs_b1 : xs_b0;
#pragma unroll
            for (int nt = 0; nt < 8; nt++) {
                uint bf[2];
                LDSM_X2_T(bf[0], bf[1], xsb + nt * 16);
                mma16816(c[nt], wa, bf);
            }
        }
    }

    // write out: rows m0+g, m0+g+8 (within 64-block), cols n0 + nt*8 + qd*2
    int g = lane >> 2, qd = lane & 3;
    int p0 = (m0 & 63) + g;
    const float* Bi = a.b[src * 3 + pid_l];
    float bv0 = Bi[p0], bv1 = Bi[p0 + 8];
    if (pid_l == 0) { bv0 *= QS; bv1 *= QS; }
    size_t rbase = (((size_t)(src * 3 + pid_l) * Bn + bb) * Pp + p0) * Nn + n0;
    uint* orow0 = (uint*)(g_projh + rbase);
    uint* orow1 = (uint*)(g_projh + rbase + (size_t)8 * Nn);
#pragma unroll
    for (int nt = 0; nt < 8; nt++) {
        orow0[nt * 4 + qd] = bfx2(fpack(c[nt][0] + bv0, c[nt][1] + bv0));
        orow1[nt * 4 + qd] = bfx2(fpack(c[nt][2] + bv1, c[nt][3] + bv1));
    }
}

// ---------------- Flash attention on mma.sync (8 warps; bf16 inputs) ----------------
__global__ __launch_bounds__(256) void fa_mma_kernel() {
    __shared__ __align__(16) __nv_bfloat16 Qs[128][24];
    __shared__ __align__(16) __nv_bfloat16 KTs[16][136];
    __shared__ __align__(16) __nv_bfloat16 VTs[16][136];

    int tid = threadIdx.x, lane = tid & 31, wid = tid >> 5;
    int it = blockIdx.x, z = blockIdx.y;
    int branch = z >> 4, bb = (z >> 2) & 3, h = z & 3;
    int i0 = it * 128;

    int qid = branch ? 3 : 0;
    int kid = branch ? 1 : 4;
    int vid = branch ? 2 : 5;
    const uint* qb = (const uint*)(g_projh + (((size_t)qid * Bn + bb) * Pp + h * Dd) * Nn);
    const uint* kb = (const uint*)(g_projh + (((size_t)kid * Bn + bb) * Pp + h * Dd) * Nn);
    const uint* vb = (const uint*)(g_projh + (((size_t)vid * Bn + bb) * Pp + h * Dd) * Nn);

    // Q tile copy (already QS-scaled bf16)
#pragma unroll
    for (int r = 0; r < 4; r++) {
        int s = tid + r * 256;
        int d = s >> 6, m2 = (s & 63) << 1;
        uint v = qb[(d * Nn + i0 + m2) >> 1];
        *(ushort_t*)&Qs[m2][d]     = (ushort_t)v;
        *(ushort_t*)&Qs[m2 + 1][d] = (ushort_t)(v >> 16);
    }
    __syncthreads();

    uint qa[4];
    {
        int m0 = wid * 16;
        uint addr = smem_u32(&Qs[m0 + (lane & 15)][(lane >> 4) * 8]);
        LDSM_X4(qa[0], qa[1], qa[2], qa[3], addr);
    }

    float o[2][4] = {};
    float o2[4] = {};
    const uint ones[2] = {0x3F803F80u, 0x3F803F80u};

    uint kt_base = smem_u32(&KTs[lane & 15][0]);
    uint vt_base0 = smem_u32(&VTs[lane & 7][((lane >> 3) & 1) * 8]);
    uint vt_base1 = smem_u32(&VTs[8 + (lane & 7)][((lane >> 3) & 1) * 8]);

    int ld_d[4], ld_j[4];
#pragma unroll
    for (int r = 0; r < 4; r++) {
        int s = tid + r * 256;
        ld_d[r] = s >> 6;
        ld_j[r] = (s & 63) << 1;
    }

    uint kpre[4], vpre[4];
#pragma unroll
    for (int r = 0; r < 4; r++) {
        kpre[r] = kb[(ld_d[r] * Nn + ld_j[r]) >> 1];
        vpre[r] = vb[(ld_d[r] * Nn + ld_j[r]) >> 1];
    }

    for (int t = 0; t < 32; t++) {
        __syncthreads();
#pragma unroll
        for (int r = 0; r < 4; r++) {
            *(uint*)&KTs[ld_d[r]][ld_j[r]] = kpre[r];
            *(uint*)&VTs[ld_d[r]][ld_j[r]] = vpre[r];
        }
        __syncthreads();

        if (t < 31) {
            int j0n = (t + 1) * 128;
#pragma unroll
            for (int r = 0; r < 4; r++) {
                kpre[r] = kb[(ld_d[r] * Nn + j0n + ld_j[r]) >> 1];
                vpre[r] = vb[(ld_d[r] * Nn + j0n + ld_j[r]) >> 1];
            }
        }

#pragma unroll
        for (int kc = 0; kc < 8; kc++) {
            int jb = kc * 16;
            uint kf0[2], kf1[2], vf0[2], vf1[2];
            LDSM_X2_T(kf0[0], kf0[1], kt_base + jb * 2);
            LDSM_X2_T(kf1[0], kf1[1], kt_base + jb * 2 + 16);
            LDSM_X2(vf0[0], vf0[1], vt_base0 + jb * 2);
            LDSM_X2(vf1[0], vf1[1], vt_base1 + jb * 2);

            float c0[4] = {0.f, 0.f, 0.f, 0.f};
            float c1[4] = {0.f, 0.f, 0.f, 0.f};
            mma16816(c0, qa, kf0);
            mma16816(c1, qa, kf1);
            ull p01 = pexp2(fpack(c0[0], c0[1]));
            ull p23 = pexp2(fpack(c0[2], c0[3]));
            ull q01 = pexp2(fpack(c1[0], c1[1]));
            ull q23 = pexp2(fpack(c1[2], c1[3]));
            uint pa[4];
            pa[0] = bfx2(p01);
            pa[1] = bfx2(p23);
            pa[2] = bfx2(q01);
            pa[3] = bfx2(q23);
            mma16816(o[0], pa, vf0);
            mma16816(o[1], pa, vf1);
            mma16816(o2, pa, ones);
        }
    }

    float* ob = g_attn + (((size_t)branch * Bn + bb) * Pp + h * Dd) * Nn;
    int g = lane >> 2, qd = lane & 3;
    int m0 = wid * 16;
    float ig = 1.f / o2[0];
    float ih = 1.f / o2[2];
    int iq = i0 + m0 + g;
#pragma unroll
    for (int dt = 0; dt < 2; dt++) {
        int d = dt * 8 + qd * 2;
        ob[(size_t)d * Nn + iq]           = o[dt][0] * ig;
        ob[(size_t)(d + 1) * Nn + iq]     = o[dt][1] * ig;
        ob[(size_t)d * Nn + iq + 8]       = o[dt][2] * ih;
        ob[(size_t)(d + 1) * Nn + iq + 8] = o[dt][3] * ih;
    }
}

// ---------------- Output projection + residual + group partial sums ----------------
__global__ __launch_bounds__(256) void outproj_kernel(
    const float* __restrict__ fa, const float* __restrict__ fb,
    const float* __restrict__ owa, const float* __restrict__ oba,
    const float* __restrict__ owb, const float* __restrict__ obb,
    float* __restrict__ dout) {
    int z = blockIdx.z;
    int branch = z >> 2, bb = z & 3;
    int c0 = blockIdx.x * 64;
    int n0 = blockIdx.y * 64;
    const float* OW = branch ? owb : owa;
    const float* OB = branch ? obb : oba;
    const float* F  = (branch ? fb : fa) + (size_t)bb * Cc * Nn;
    const float* O  = g_attn + ((size_t)branch * Bn + bb) * Pp * Nn;

    __shared__ float OWs[64][65];
    __shared__ float Os[64][68];
    __shared__ float RS[16][17], RS2[16][17];

    int tid = threadIdx.x, tx = tid & 15, ty = tid >> 4;
#pragma unroll
    for (int r = 0; r < 4; r++) {
        int e = tid + r * 256;
        int cl = e >> 4;
        int p4 = (e & 15) << 2;
        float4 wv = *(const float4*)(OW + (size_t)(c0 + cl) * Pp + p4);
        OWs[p4 + 0][cl] = wv.x; OWs[p4 + 1][cl] = wv.y;
        OWs[p4 + 2][cl] = wv.z; OWs[p4 + 3][cl] = wv.w;
        int p = e >> 4;
        int nl = (e & 15) << 2;
        *(float4*)&Os[p][nl] = *(const float4*)(O + (size_t)p * Nn + n0 + nl);
    }
    __syncthreads();

    float acc[4][4] = {};
#pragma unroll 4
    for (int p = 0; p < 64; p++) {
        float a0 = OWs[p][ty * 4 + 0], a1 = OWs[p][ty * 4 + 1];
        float a2 = OWs[p][ty * 4 + 2], a3 = OWs[p][ty * 4 + 3];
        float4 xv = *(const float4*)&Os[p][tx * 4];
        acc[0][0] = fmaf(a0, xv.x, acc[0][0]); acc[0][1] = fmaf(a0, xv.y, acc[0][1]);
        acc[0][2] = fmaf(a0, xv.z, acc[0][2]); acc[0][3] = fmaf(a0, xv.w, acc[0][3]);
        acc[1][0] = fmaf(a1, xv.x, acc[1][0]); acc[1][1] = fmaf(a1, xv.y, acc[1][1]);
        acc[1][2] = fmaf(a1, xv.z, acc[1][2]); acc[1][3] = fmaf(a1, xv.w, acc[1][3]);
        acc[2][0] = fmaf(a2, xv.x, acc[2][0]); acc[2][1] = fmaf(a2, xv.y, acc[2][1]);
        acc[2][2] = fmaf(a2, xv.z, acc[2][2]); acc[2][3] = fmaf(a2, xv.w, acc[2][3]);
        acc[3][0] = fmaf(a3, xv.x, acc[3][0]); acc[3][1] = fmaf(a3, xv.y, acc[3][1]);
        acc[3][2] = fmaf(a3, xv.z, acc[3][2]); acc[3][3] = fmaf(a3, xv.w, acc[3][3]);
    }
    size_t obase = (size_t)branch * Bn * Cc * Nn + (size_t)bb * Cc * Nn;
    float ls = 0.f, ls2 = 0.f;
#pragma unroll
    for (int i = 0; i < 4; i++) {
        int c = c0 + ty * 4 + i;
        float bv = OB[c];
        float4 fv = *(const float4*)(F + (size_t)c * Nn + n0 + tx * 4);
        float4 r = make_float4(acc[i][0] + bv + fv.x, acc[i][1] + bv + fv.y,
                               acc[i][2] + bv + fv.z, acc[i][3] + bv + fv.w);
        ls  += r.x + r.y + r.z + r.w;
        ls2 += r.x * r.x + r.y * r.y + r.z * r.z + r.w * r.w;
        *(float4*)(dout + obase + (size_t)c * Nn + n0 + tx * 4) = r;
    }

    RS[ty][tx] = ls;
    RS2[ty][tx] = ls2;
    __syncthreads();
    if (tid < 64) {
        int gl = tid >> 4, cc = tid & 15;
        float s  = RS[gl * 4 + 0][cc] + RS[gl * 4 + 1][cc] + RS[gl * 4 + 2][cc] + RS[gl * 4 + 3][cc];
        float s2 = RS2[gl * 4 + 0][cc] + RS2[gl * 4 + 1][cc] + RS2[gl * 4 + 2][cc] + RS2[gl * 4 + 3][cc];
#pragma unroll
        for (int st = 8; st > 0; st >>= 1) {
            s  += __shfl_xor_sync(0xFFFFFFFFu, s, st);
            s2 += __shfl_xor_sync(0xFFFFFFFFu, s2, st);
        }
        if (cc == 0) {
            int gidx = blockIdx.x * 4 + gl;
            float* pp = g_part + (((size_t)z * 16 + gidx) * 64 + blockIdx.y) * 2;
            pp[0] = s;
            pp[1] = s2;
        }
    }
}

// ---------------- final stats ----------------
__global__ __launch_bounds__(64) void stats_final_kernel() {
    int gidx = blockIdx.x;
    int tid = threadIdx.x;
    const float* pp = g_part + ((size_t)gidx * 64 + tid) * 2;
    float s = pp[0], s2 = pp[1];
#pragma unroll
    for (int st = 16; st > 0; st >>= 1) {
        s  += __shfl_xor_sync(0xFFFFFFFFu, s, st);
        s2 += __shfl_xor_sync(0xFFFFFFFFu, s2, st);
    }
    __shared__ float sh[2], sh2[2];
    if ((tid & 31) == 0) { sh[tid >> 5] = s; sh2[tid >> 5] = s2; }
    __syncthreads();
    if (tid == 0) {
        float S = sh[0] + sh[1], S2 = sh2[0] + sh2[1];
        float mean = S * (1.f / 65536.f);
        float var  = S2 * (1.f / 65536.f) - mean * mean;
        g_stats[gidx * 2 + 0] = mean;
        g_stats[gidx * 2 + 1] = rsqrtf(var + 1e-5f);
    }
}

// ---------------- Normalize in place ----------------
__global__ __launch_bounds__(256) void norm_kernel(float* __restrict__ dout,
                                                   const float* __restrict__ ga, const float* __restrict__ bta,
                                                   const float* __restrict__ gb, const float* __restrict__ btb) {
    size_t qi = (size_t)blockIdx.x * blockDim.x + threadIdx.x;
    if (qi >= (size_t)2 * Bn * Cc * Nn / 4) return;
    size_t e = qi * 4;
    int branch = (int)(e >> 22);
    size_t r = e & ((1ull << 22) - 1);
    int c = (int)((r >> 12) & 255);
    int bb = (int)(r >> 20);
    int g = c >> 4;
    int sidx = (branch * 4 + bb) * 16 + g;
    float mean = g_stats[sidx * 2 + 0];
    float rstd = g_stats[sidx * 2 + 1];
    float gamma = (branch ? gb : ga)[c];
    float beta  = (branch ? btb : bta)[c];
    float aa = rstd * gamma;
    float bc = beta - mean * aa;
    float4 v = *(float4*)(dout + e);
    v.x = fmaf(v.x, aa, bc); v.y = fmaf(v.y, aa, bc);
    v.z = fmaf(v.z, aa, bc); v.w = fmaf(v.w, aa, bc);
    *(float4*)(dout + e) = v;
}

extern "C" void kernel_launch(void* const* d_in, const int* in_sizes, int n_in,
                              void* d_out, int out_size) {
    const float* feat_a = (const float*)d_in[0];
    const float* feat_b = (const float*)d_in[1];

    ProjArgs pa;
    pa.x[0] = feat_a; pa.x[1] = feat_b;
    pa.w[0] = (const float*)d_in[2];  pa.b[0] = (const float*)d_in[3];   // q_a
    pa.w[1] = (const float*)d_in[10]; pa.b[1] = (const float*)d_in[11];  // k_a
    pa.w[2] = (const float*)d_in[12]; pa.b[2] = (const float*)d_in[13];  // v_a
    pa.w[3] = (const float*)d_in[8];  pa.b[3] = (const float*)d_in[9];   // q_b
    pa.w[4] = (const float*)d_in[4];  pa.b[4] = (const float*)d_in[5];   // k_b
    pa.w[5] = (const float*)d_in[6];  pa.b[5] = (const float*)d_in[7];   // v_b

    float* dout = (float*)d_out;

    dim3 pg(Nn / 64, Bn, 2);
    proj_mma_kernel<<<pg, 384>>>(pa);

    dim3 fg(Nn / 128, 2 * Bn * Hh);
    fa_mma_kernel<<<fg, 256>>>();

    dim3 og(Cc / 64, Nn / 64, 2 * Bn);
    outproj_kernel<<<og, 256>>>(feat_a, feat_b,
                                (const float*)d_in[14], (const float*)d_in[15],
                                (const float*)d_in[16], (const float*)d_in[17],
                                dout);

    stats_final_kernel<<<128, 64>>>();

    size_t nvec = (size_t)2 * Bn * Cc * Nn / 4;
    norm_kernel<<<(unsigned)((nvec + 255) / 256), 256>>>(dout,
                                (const float*)d_in[18], (const float*)d_in[19],
                                (const float*)d_in[20], (const float*)d_in[21]);
}

// round 10
// speedup vs baseline: 1.4825x; 1.0372x over previous
#include <cuda_runtime.h>
#include <cuda_bf16.h>

#define Bn 4
#define Cc 256
#define Pp 64
#define Hh 4
#define Dd 16
#define Nn 4096

typedef unsigned long long ull;
typedef unsigned int uint;
typedef unsigned short ushort_t;

// Scratch (device globals; no allocation allowed)
__device__ __nv_bfloat16 g_projh[6 * Bn * Pp * Nn];  // [pid][b][p][n] bf16; q pre-scaled
__device__ __nv_bfloat16 g_attnh[2 * Bn * Pp * Nn];  // [branch][b][p][n] bf16
__device__ float g_part[8 * 16 * 64 * 2];            // per (z,group,ntile): s, s2
__device__ float g_stats[2 * Bn * 16 * 2];           // mean, rstd

struct ProjArgs {
    const float* x[2];
    const float* w[6];
    const float* b[6];
};

// ---- packed f32x2 ops (FMA pipe) ----
#define PFMA(d, a, b, c) asm("fma.rn.f32x2 %0,%1,%2,%3;" : "=l"(d) : "l"(a), "l"(b), "l"(c))
#define PADD(d, a, b)    asm("add.rn.f32x2 %0,%1,%2;"    : "=l"(d) : "l"(a), "l"(b))

__device__ __forceinline__ ull fdup(float x) {
    uint u = __float_as_uint(x);
    return ((ull)u << 32) | u;
}
__device__ __forceinline__ ull fpack(float lo, float hi) {
    return ((ull)__float_as_uint(hi) << 32) | __float_as_uint(lo);
}

// packed 2^t: round trick + degree-3 Taylor + exponent splice.
__device__ __forceinline__ ull pexp2(ull t) {
    ull r, fi, f, p;
    PADD(r, t, fdup(12582912.f));
    PADD(fi, r, fdup(-12582912.f));
    PFMA(f, fi, fdup(-1.f), t);
    p = fdup(5.55041087e-2f);
    PFMA(p, p, f, fdup(2.40226507e-1f));
    PFMA(p, p, f, fdup(6.93147181e-1f));
    PFMA(p, p, f, fdup(1.0f));
    uint lo = (uint)p + ((uint)r << 23);
    uint hi = (uint)(p >> 32) + ((uint)(r >> 32) << 23);
    return ((ull)hi << 32) | lo;
}

__device__ __forceinline__ uint smem_u32(const void* p) {
    uint a;
    asm("{ .reg .u64 t; cvta.to.shared.u64 t, %1; cvt.u32.u64 %0, t; }" : "=r"(a) : "l"(p));
    return a;
}

__device__ __forceinline__ uint bfx2(ull p) {
    float lo = __uint_as_float((uint)p);
    float hi = __uint_as_float((uint)(p >> 32));
    uint r;
    asm("cvt.rn.bf16x2.f32 %0, %1, %2;" : "=r"(r) : "f"(hi), "f"(lo));
    return r;
}

#define LDSM_X4(r0, r1, r2, r3, a) \
    asm volatile("ldmatrix.sync.aligned.m8n8.x4.shared.b16 {%0,%1,%2,%3}, [%4];" \
        : "=r"(r0), "=r"(r1), "=r"(r2), "=r"(r3) : "r"(a))
#define LDSM_X2(r0, r1, a) \
    asm volatile("ldmatrix.sync.aligned.m8n8.x2.shared.b16 {%0,%1}, [%2];" \
        : "=r"(r0), "=r"(r1) : "r"(a))
#define LDSM_X2_T(r0, r1, a) \
    asm volatile("ldmatrix.sync.aligned.m8n8.x2.trans.shared.b16 {%0,%1}, [%2];" \
        : "=r"(r0), "=r"(r1) : "r"(a))

__device__ __forceinline__ void mma16816(float* c, const uint* a, const uint* b) {
    asm volatile(
        "mma.sync.aligned.m16n8k16.row.col.f32.bf16.bf16.f32 "
        "{%0,%1,%2,%3}, {%4,%5,%6,%7}, {%8,%9}, {%0,%1,%2,%3};"
        : "+f"(c[0]), "+f"(c[1]), "+f"(c[2]), "+f"(c[3])
        : "r"(a[0]), "r"(a[1]), "r"(a[2]), "r"(a[3]), "r"(b[0]), "r"(b[1]));
}

// ---------------- QKV projection on tensor cores ----------------
__global__ __launch_bounds__(384) void proj_mma_kernel(ProjArgs a) {
    __shared__ __align__(16) __nv_bfloat16 Wt[192][40];
    __shared__ __align__(16) __nv_bfloat16 Xs[32][72];

    int tid = threadIdx.x, lane = tid & 31, wid = tid >> 5;
    int n0 = blockIdx.x * 64;
    int bb = blockIdx.y;
    int src = blockIdx.z;
    const float* X = a.x[src] + (size_t)bb * Cc * Nn;
    const float QS = 0.25f * 1.4426950408889634f;

    int m0 = wid * 16;
    int pid_l = m0 >> 6;

    float c[8][4] = {};
    uint xs_b0 = smem_u32(&Xs[lane & 15][0]);
    uint xs_b1 = smem_u32(&Xs[16 + (lane & 15)][0]);

    for (int s8 = 0; s8 < 8; s8++) {
        int k0 = s8 * 32;
        __syncthreads();
#pragma unroll
        for (int r = 0; r < 4; r++) {
            int e = tid + r * 384;
            int m = e >> 3;
            int cc4 = (e & 7) << 2;
            int wsel = m >> 6;
            int p = m & 63;
            float4 wv = *(const float4*)(a.w[src * 3 + wsel] + (size_t)p * Cc + k0 + cc4);
            if (wsel == 0) { wv.x *= QS; wv.y *= QS; wv.z *= QS; wv.w *= QS; }
            uint* wr = (uint*)&Wt[m][cc4];
            wr[0] = bfx2(fpack(wv.x, wv.y));
            wr[1] = bfx2(fpack(wv.z, wv.w));
        }
        for (int s = tid; s < 1024; s += 384) {
            int k = s >> 5;
            int n2 = (s & 31) << 1;
            float2 xv = *(const float2*)(X + (size_t)(k0 + k) * Nn + n0 + n2);
            *(uint*)&Xs[k][n2] = bfx2(fpack(xv.x, xv.y));
        }
        __syncthreads();

#pragma unroll
        for (int ks = 0; ks < 2; ks++) {
            uint wa[4];
            uint aaddr = smem_u32(&Wt[m0 + (lane & 15)][ks * 16 + (lane >> 4) * 8]);
            LDSM_X4(wa[0], wa[1], wa[2], wa[3], aaddr);
            uint xsb = ks ? xs_b1 : xs_b0;
#pragma unroll
            for (int nt = 0; nt < 8; nt++) {
                uint bf[2];
                LDSM_X2_T(bf[0], bf[1], xsb + nt * 16);
                mma16816(c[nt], wa, bf);
            }
        }
    }

    int g = lane >> 2, qd = lane & 3;
    int p0 = (m0 & 63) + g;
    const float* Bi = a.b[src * 3 + pid_l];
    float bv0 = Bi[p0], bv1 = Bi[p0 + 8];
    if (pid_l == 0) { bv0 *= QS; bv1 *= QS; }
    size_t rbase = (((size_t)(src * 3 + pid_l) * Bn + bb) * Pp + p0) * Nn + n0;
    uint* orow0 = (uint*)(g_projh + rbase);
    uint* orow1 = (uint*)(g_projh + rbase + (size_t)8 * Nn);
#pragma unroll
    for (int nt = 0; nt < 8; nt++) {
        orow0[nt * 4 + qd] = bfx2(fpack(c[nt][0] + bv0, c[nt][1] + bv0));
        orow1[nt * 4 + qd] = bfx2(fpack(c[nt][2] + bv1, c[nt][3] + bv1));
    }
}

// ---------------- Flash attention on mma.sync (8 warps; bf16 in/out) ----------------
__global__ __launch_bounds__(256) void fa_mma_kernel() {
    __shared__ __align__(16) __nv_bfloat16 Qs[128][24];
    __shared__ __align__(16) __nv_bfloat16 KTs[16][136];
    __shared__ __align__(16) __nv_bfloat16 VTs[16][136];

    int tid = threadIdx.x, lane = tid & 31, wid = tid >> 5;
    int it = blockIdx.x, z = blockIdx.y;
    int branch = z >> 4, bb = (z >> 2) & 3, h = z & 3;
    int i0 = it * 128;

    int qid = branch ? 3 : 0;
    int kid = branch ? 1 : 4;
    int vid = branch ? 2 : 5;
    const uint* qb = (const uint*)(g_projh + (((size_t)qid * Bn + bb) * Pp + h * Dd) * Nn);
    const uint* kb = (const uint*)(g_projh + (((size_t)kid * Bn + bb) * Pp + h * Dd) * Nn);
    const uint* vb = (const uint*)(g_projh + (((size_t)vid * Bn + bb) * Pp + h * Dd) * Nn);

#pragma unroll
    for (int r = 0; r < 4; r++) {
        int s = tid + r * 256;
        int d = s >> 6, m2 = (s & 63) << 1;
        uint v = qb[(d * Nn + i0 + m2) >> 1];
        *(ushort_t*)&Qs[m2][d]     = (ushort_t)v;
        *(ushort_t*)&Qs[m2 + 1][d] = (ushort_t)(v >> 16);
    }
    __syncthreads();

    uint qa[4];
    {
        int m0 = wid * 16;
        uint addr = smem_u32(&Qs[m0 + (lane & 15)][(lane >> 4) * 8]);
        LDSM_X4(qa[0], qa[1], qa[2], qa[3], addr);
    }

    float o[2][4] = {};
    float o2[4] = {};
    const uint ones[2] = {0x3F803F80u, 0x3F803F80u};

    uint kt_base = smem_u32(&KTs[lane & 15][0]);
    uint vt_base0 = smem_u32(&VTs[lane & 7][((lane >> 3) & 1) * 8]);
    uint vt_base1 = smem_u32(&VTs[8 + (lane & 7)][((lane >> 3) & 1) * 8]);

    int ld_d[4], ld_j[4];
#pragma unroll
    for (int r = 0; r < 4; r++) {
        int s = tid + r * 256;
        ld_d[r] = s >> 6;
        ld_j[r] = (s & 63) << 1;
    }

    uint kpre[4], vpre[4];
#pragma unroll
    for (int r = 0; r < 4; r++) {
        kpre[r] = kb[(ld_d[r] * Nn + ld_j[r]) >> 1];
        vpre[r] = vb[(ld_d[r] * Nn + ld_j[r]) >> 1];
    }

    for (int t = 0; t < 32; t++) {
        __syncthreads();
#pragma unroll
        for (int r = 0; r < 4; r++) {
            *(uint*)&KTs[ld_d[r]][ld_j[r]] = kpre[r];
            *(uint*)&VTs[ld_d[r]][ld_j[r]] = vpre[r];
        }
        __syncthreads();

        if (t < 31) {
            int j0n = (t + 1) * 128;
#pragma unroll
            for (int r = 0; r < 4; r++) {
                kpre[r] = kb[(ld_d[r] * Nn + j0n + ld_j[r]) >> 1];
                vpre[r] = vb[(ld_d[r] * Nn + j0n + ld_j[r]) >> 1];
            }
        }

#pragma unroll
        for (int kc = 0; kc < 8; kc++) {
            int jb = kc * 16;
            uint kf0[2], kf1[2], vf0[2], vf1[2];
            LDSM_X2_T(kf0[0], kf0[1], kt_base + jb * 2);
            LDSM_X2_T(kf1[0], kf1[1], kt_base + jb * 2 + 16);
            LDSM_X2(vf0[0], vf0[1], vt_base0 + jb * 2);
            LDSM_X2(vf1[0], vf1[1], vt_base1 + jb * 2);

            float c0[4] = {0.f, 0.f, 0.f, 0.f};
            float c1[4] = {0.f, 0.f, 0.f, 0.f};
            mma16816(c0, qa, kf0);
            mma16816(c1, qa, kf1);
            ull p01 = pexp2(fpack(c0[0], c0[1]));
            ull p23 = pexp2(fpack(c0[2], c0[3]));
            ull q01 = pexp2(fpack(c1[0], c1[1]));
            ull q23 = pexp2(fpack(c1[2], c1[3]));
            uint pa[4];
            pa[0] = bfx2(p01);
            pa[1] = bfx2(p23);
            pa[2] = bfx2(q01);
            pa[3] = bfx2(q23);
            mma16816(o[0], pa, vf0);
            mma16816(o[1], pa, vf1);
            mma16816(o2, pa, ones);
        }
    }

    __nv_bfloat16* ob = g_attnh + (((size_t)branch * Bn + bb) * Pp + h * Dd) * Nn;
    int g = lane >> 2, qd = lane & 3;
    int m0 = wid * 16;
    float ig = 1.f / o2[0];
    float ih = 1.f / o2[2];
    int iq = i0 + m0 + g;
#pragma unroll
    for (int dt = 0; dt < 2; dt++) {
        int d = dt * 8 + qd * 2;
        ob[(size_t)d * Nn + iq]           = __float2bfloat16(o[dt][0] * ig);
        ob[(size_t)(d + 1) * Nn + iq]     = __float2bfloat16(o[dt][1] * ig);
        ob[(size_t)d * Nn + iq + 8]       = __float2bfloat16(o[dt][2] * ih);
        ob[(size_t)(d + 1) * Nn + iq + 8] = __float2bfloat16(o[dt][3] * ih);
    }
}

// ---------------- Output projection on tensor cores + residual + partials ----------------
// CTA = (z = branch*4+b, 64-wide n tile). 8 warps; warp w owns c rows w*32..w*32+31.
__global__ __launch_bounds__(256) void outproj_mma_kernel(
    const float* __restrict__ fa, const float* __restrict__ fb,
    const float* __restrict__ owa, const float* __restrict__ oba,
    const float* __restrict__ owb, const float* __restrict__ obb,
    float* __restrict__ dout) {
    __shared__ __align__(16) __nv_bfloat16 OWs[256][72];  // [c][p]
    __shared__ __align__(16) __nv_bfloat16 Os[64][72];    // [p][n]

    int tid = threadIdx.x, lane = tid & 31, wid = tid >> 5;
    int n0 = blockIdx.x * 64;
    int z = blockIdx.y;
    int branch = z >> 2, bb = z & 3;
    const float* OW = branch ? owb : owa;
    const float* OB = branch ? obb : oba;
    const float* F  = (branch ? fb : fa) + (size_t)bb * Cc * Nn;
    const __nv_bfloat16* O = g_attnh + ((size_t)branch * Bn + bb) * Pp * Nn;

    for (int s = tid; s < 8192; s += 256) {
        int c = s >> 5, p2 = (s & 31) << 1;
        float2 wv = *(const float2*)(OW + (size_t)c * Pp + p2);
        *(uint*)&OWs[c][p2] = bfx2(fpack(wv.x, wv.y));
    }
    for (int s = tid; s < 2048; s += 256) {
        int p = s >> 5, n2 = (s & 31) << 1;
        *(uint*)&Os[p][n2] = *(const uint*)(O + (size_t)p * Nn + n0 + n2);
    }
    __syncthreads();

    // A-fragments: 2 m-tiles x 4 k-chunks
    uint wa[2][4][4];
#pragma unroll
    for (int mt = 0; mt < 2; mt++)
#pragma unroll
        for (int kc = 0; kc < 4; kc++) {
            uint addr = smem_u32(&OWs[wid * 32 + mt * 16 + (lane & 15)][kc * 16 + (lane >> 4) * 8]);
            LDSM_X4(wa[mt][kc][0], wa[mt][kc][1], wa[mt][kc][2], wa[mt][kc][3], addr);
        }

    float c[2][8][4] = {};
#pragma unroll
    for (int kc = 0; kc < 4; kc++) {
        uint brow = smem_u32(&Os[kc * 16 + (lane & 15)][0]);
#pragma unroll
        for (int nt = 0; nt < 8; nt++) {
            uint bf[2];
            LDSM_X2_T(bf[0], bf[1], brow + nt * 16);
            mma16816(c[0][nt], wa[0][kc], bf);
            mma16816(c[1][nt], wa[1][kc], bf);
        }
    }

    // epilogue: bias + residual + write + group partials
    size_t obase = (size_t)z * Cc * Nn;
    int g = lane >> 2, qd = lane & 3;
    float lsv[2] = {0.f, 0.f}, ls2v[2] = {0.f, 0.f};
#pragma unroll
    for (int mt = 0; mt < 2; mt++) {
        int c0r = wid * 32 + mt * 16 + g;
        float bv0 = OB[c0r], bv1 = OB[c0r + 8];
        size_t base0 = obase + (size_t)c0r * Nn + n0;
        size_t fb0 = (size_t)c0r * Nn + n0;
#pragma unroll
        for (int nt = 0; nt < 8; nt++) {
            int col = nt * 8 + qd * 2;
            float2 f0 = *(const float2*)(F + fb0 + col);
            float2 f1 = *(const float2*)(F + fb0 + (size_t)8 * Nn + col);
            float r0 = c[mt][nt][0] + bv0 + f0.x;
            float r1 = c[mt][nt][1] + bv0 + f0.y;
            float r2 = c[mt][nt][2] + bv1 + f1.x;
            float r3 = c[mt][nt][3] + bv1 + f1.y;
            lsv[mt]  += r0 + r1 + r2 + r3;
            ls2v[mt] += r0 * r0 + r1 * r1 + r2 * r2 + r3 * r3;
            float2 w0 = make_float2(r0, r1), w1 = make_float2(r2, r3);
            *(float2*)(dout + base0 + col) = w0;
            *(float2*)(dout + base0 + (size_t)8 * Nn + col) = w1;
        }
    }
#pragma unroll
    for (int mt = 0; mt < 2; mt++) {
        float s = lsv[mt], s2 = ls2v[mt];
#pragma unroll
        for (int st = 16; st > 0; st >>= 1) {
            s  += __shfl_xor_sync(0xFFFFFFFFu, s, st);
            s2 += __shfl_xor_sync(0xFFFFFFFFu, s2, st);
        }
        if (lane == 0) {
            int gidx = wid * 2 + mt;
            float* pp = g_part + (((size_t)z * 16 + gidx) * 64 + blockIdx.x) * 2;
            pp[0] = s;
            pp[1] = s2;
        }
    }
}

// ---------------- final stats ----------------
__global__ __launch_bounds__(64) void stats_final_kernel() {
    int gidx = blockIdx.x;
    int tid = threadIdx.x;
    const float* pp = g_part + ((size_t)gidx * 64 + tid) * 2;
    float s = pp[0], s2 = pp[1];
#pragma unroll
    for (int st = 16; st > 0; st >>= 1) {
        s  += __shfl_xor_sync(0xFFFFFFFFu, s, st);
        s2 += __shfl_xor_sync(0xFFFFFFFFu, s2, st);
    }
    __shared__ float sh[2], sh2[2];
    if ((tid & 31) == 0) { sh[tid >> 5] = s; sh2[tid >> 5] = s2; }
    __syncthreads();
    if (tid == 0) {
        float S = sh[0] + sh[1], S2 = sh2[0] + sh2[1];
        float mean = S * (1.f / 65536.f);
        float var  = S2 * (1.f / 65536.f) - mean * mean;
        g_stats[gidx * 2 + 0] = mean;
        g_stats[gidx * 2 + 1] = rsqrtf(var + 1e-5f);
    }
}

// ---------------- Normalize in place ----------------
__global__ __launch_bounds__(256) void norm_kernel(float* __restrict__ dout,
                                                   const float* __restrict__ ga, const float* __restrict__ bta,
                                                   const float* __restrict__ gb, const float* __restrict__ btb) {
    size_t qi = (size_t)blockIdx.x * blockDim.x + threadIdx.x;
    if (qi >= (size_t)2 * Bn * Cc * Nn / 4) return;
    size_t e = qi * 4;
    int branch = (int)(e >> 22);
    size_t r = e & ((1ull << 22) - 1);
    int c = (int)((r >> 12) & 255);
    int bb = (int)(r >> 20);
    int g = c >> 4;
    int sidx = (branch * 4 + bb) * 16 + g;
    float mean = g_stats[sidx * 2 + 0];
    float rstd = g_stats[sidx * 2 + 1];
    float gamma = (branch ? gb : ga)[c];
    float beta  = (branch ? btb : bta)[c];
    float aa = rstd * gamma;
    float bc = beta - mean * aa;
    float4 v = *(float4*)(dout + e);
    v.x = fmaf(v.x, aa, bc); v.y = fmaf(v.y, aa, bc);
    v.z = fmaf(v.z, aa, bc); v.w = fmaf(v.w, aa, bc);
    *(float4*)(dout + e) = v;
}

extern "C" void kernel_launch(void* const* d_in, const int* in_sizes, int n_in,
                              void* d_out, int out_size) {
    const float* feat_a = (const float*)d_in[0];
    const float* feat_b = (const float*)d_in[1];

    ProjArgs pa;
    pa.x[0] = feat_a; pa.x[1] = feat_b;
    pa.w[0] = (const float*)d_in[2];  pa.b[0] = (const float*)d_in[3];   // q_a
    pa.w[1] = (const float*)d_in[10]; pa.b[1] = (const float*)d_in[11];  // k_a
    pa.w[2] = (const float*)d_in[12]; pa.b[2] = (const float*)d_in[13];  // v_a
    pa.w[3] = (const float*)d_in[8];  pa.b[3] = (const float*)d_in[9];   // q_b
    pa.w[4] = (const float*)d_in[4];  pa.b[4] = (const float*)d_in[5];   // k_b
    pa.w[5] = (const float*)d_in[6];  pa.b[5] = (const float*)d_in[7];   // v_b

    float* dout = (float*)d_out;

    dim3 pg(Nn / 64, Bn, 2);
    proj_mma_kernel<<<pg, 384>>>(pa);

    dim3 fg(Nn / 128, 2 * Bn * Hh);
    fa_mma_kernel<<<fg, 256>>>();

    dim3 og(Nn / 64, 2 * Bn);
    outproj_mma_kernel<<<og, 256>>>(feat_a, feat_b,
                                    (const float*)d_in[14], (const float*)d_in[15],
                                    (const float*)d_in[16], (const float*)d_in[17],
                                    dout);

    stats_final_kernel<<<128, 64>>>();

    size_t nvec = (size_t)2 * Bn * Cc * Nn / 4;
    norm_kernel<<<(unsigned)((nvec + 255) / 256), 256>>>(dout,
                                (const float*)d_in[18], (const float*)d_in[19],
                                (const float*)d_in[20], (const float*)d_in[21]);
}